// round 2
// baseline (speedup 1.0000x reference)
#include <cuda_runtime.h>

// Problem constants
#define BB   512      // batch
#define TT   1024     // seq len
#define TM1  1023     // T-1 recurrence steps
#define II   32       // input dim
#define EE   32       // time-encoding dim
#define HH   256      // hidden dim
#define G3   768      // 3*H gate rows
#define KIN  64       // I+E

// Launch config: each block owns BPB batch elements, persistent over all t.
#define BPB  4
#define NB   (BB / BPB)   // 128 blocks
#define NT   768          // one thread per gate row

__device__ __forceinline__ float sigf(float x) {
    return 1.0f / (1.0f + __expf(-x));
}

__global__ void __launch_bounds__(NT, 1)
arrnn_kernel(const float* __restrict__ X,
             const float* __restrict__ ENC,
             const int* __restrict__ MASK,        // bool materialized as int32
             const float* __restrict__ wih0, const float* __restrict__ whh0,
             const float* __restrict__ bih0, const float* __restrict__ bhh0,
             const float* __restrict__ wih1, const float* __restrict__ whh1,
             const float* __restrict__ bih1, const float* __restrict__ bhh1,
             const float* __restrict__ wout, const float* __restrict__ bout,
             float* __restrict__ outseq, float* __restrict__ outh1,
             int write_h1)
{
    __shared__ __align__(16) float inp_s[BPB][KIN];
    __shared__ __align__(16) float h0_s[BPB][HH];
    __shared__ __align__(16) float h1_s[BPB][HH];
    __shared__ __align__(16) float y_s[BPB][II];
    __shared__ __align__(16) float gi_s[BPB][G3];
    __shared__ __align__(16) float gh_s[BPB][G3];

    const int tid = threadIdx.x;
    const int b0  = blockIdx.x * BPB;

    // zero-init state
    for (int i = tid; i < BPB * HH; i += NT) {
        (&h0_s[0][0])[i] = 0.0f;
        (&h1_s[0][0])[i] = 0.0f;
    }
    for (int i = tid; i < BPB * II; i += NT) (&y_s[0][0])[i] = 0.0f;
    __syncthreads();

    // per-thread fixed gate row
    const int g = tid;
    const float4* wi0 = reinterpret_cast<const float4*>(wih0 + g * KIN);
    const float4* wh0 = reinterpret_cast<const float4*>(whh0 + g * HH);
    const float4* wi1 = reinterpret_cast<const float4*>(wih1 + g * HH);
    const float4* wh1 = reinterpret_cast<const float4*>(whh1 + g * HH);
    const float bi0v = bih0[g];
    const float bh0v = bhh0[g];
    const float bi1v = bih1[g];
    const float bh1v = bhh1[g];

    for (int t = 0; t < TM1; ++t) {
        // ---- Phase A: build input vector [x_or_y , e(t+1)] ----
        if (tid < BPB * KIN) {
            const int b  = tid >> 6;       // /64
            const int k  = tid & 63;
            const int gb = b0 + b;
            float v;
            if (k < II) {
                const bool keep = (t == 0) || (MASK[gb * TT + t] != 0);
                v = keep ? X[((long long)gb * TT + t) * II + k] : y_s[b][k];
            } else {
                v = ENC[((long long)gb * TT + (t + 1)) * EE + (k - II)];
            }
            inp_s[b][k] = v;
        }
        __syncthreads();

        // ---- Phase B: GRU0 gate pre-activations (gi from inp, gh from h0) ----
        {
            float ai[BPB], ah[BPB];
#pragma unroll
            for (int b = 0; b < BPB; ++b) { ai[b] = bi0v; ah[b] = bh0v; }

#pragma unroll 4
            for (int kk = 0; kk < KIN / 4; ++kk) {
                const float4 w = __ldg(&wi0[kk]);
#pragma unroll
                for (int b = 0; b < BPB; ++b) {
                    const float4 x = *reinterpret_cast<const float4*>(&inp_s[b][kk * 4]);
                    ai[b] = fmaf(w.x, x.x, ai[b]);
                    ai[b] = fmaf(w.y, x.y, ai[b]);
                    ai[b] = fmaf(w.z, x.z, ai[b]);
                    ai[b] = fmaf(w.w, x.w, ai[b]);
                }
            }
#pragma unroll 8
            for (int kk = 0; kk < HH / 4; ++kk) {
                const float4 w = __ldg(&wh0[kk]);
#pragma unroll
                for (int b = 0; b < BPB; ++b) {
                    const float4 x = *reinterpret_cast<const float4*>(&h0_s[b][kk * 4]);
                    ah[b] = fmaf(w.x, x.x, ah[b]);
                    ah[b] = fmaf(w.y, x.y, ah[b]);
                    ah[b] = fmaf(w.z, x.z, ah[b]);
                    ah[b] = fmaf(w.w, x.w, ah[b]);
                }
            }
#pragma unroll
            for (int b = 0; b < BPB; ++b) { gi_s[b][g] = ai[b]; gh_s[b][g] = ah[b]; }
        }
        __syncthreads();

        // ---- Phase C: GRU0 state update ----
        if (tid < HH) {
            const int j = tid;
#pragma unroll
            for (int b = 0; b < BPB; ++b) {
                const float r = sigf(gi_s[b][j]          + gh_s[b][j]);
                const float z = sigf(gi_s[b][j + HH]     + gh_s[b][j + HH]);
                const float n = tanhf(gi_s[b][j + 2*HH] + r * gh_s[b][j + 2*HH]);
                h0_s[b][j] = (1.0f - z) * n + z * h0_s[b][j];
            }
        }
        __syncthreads();

        // ---- Phase D: GRU1 gate pre-activations (gi from h0_new, gh from h1) ----
        {
            float ai[BPB], ah[BPB];
#pragma unroll
            for (int b = 0; b < BPB; ++b) { ai[b] = bi1v; ah[b] = bh1v; }

#pragma unroll 8
            for (int kk = 0; kk < HH / 4; ++kk) {
                const float4 w = __ldg(&wi1[kk]);
#pragma unroll
                for (int b = 0; b < BPB; ++b) {
                    const float4 x = *reinterpret_cast<const float4*>(&h0_s[b][kk * 4]);
                    ai[b] = fmaf(w.x, x.x, ai[b]);
                    ai[b] = fmaf(w.y, x.y, ai[b]);
                    ai[b] = fmaf(w.z, x.z, ai[b]);
                    ai[b] = fmaf(w.w, x.w, ai[b]);
                }
            }
#pragma unroll 8
            for (int kk = 0; kk < HH / 4; ++kk) {
                const float4 w = __ldg(&wh1[kk]);
#pragma unroll
                for (int b = 0; b < BPB; ++b) {
                    const float4 x = *reinterpret_cast<const float4*>(&h1_s[b][kk * 4]);
                    ah[b] = fmaf(w.x, x.x, ah[b]);
                    ah[b] = fmaf(w.y, x.y, ah[b]);
                    ah[b] = fmaf(w.z, x.z, ah[b]);
                    ah[b] = fmaf(w.w, x.w, ah[b]);
                }
            }
#pragma unroll
            for (int b = 0; b < BPB; ++b) { gi_s[b][g] = ai[b]; gh_s[b][g] = ah[b]; }
        }
        __syncthreads();

        // ---- Phase E: GRU1 state update ----
        if (tid < HH) {
            const int j = tid;
#pragma unroll
            for (int b = 0; b < BPB; ++b) {
                const float r = sigf(gi_s[b][j]          + gh_s[b][j]);
                const float z = sigf(gi_s[b][j + HH]     + gh_s[b][j + HH]);
                const float n = tanhf(gi_s[b][j + 2*HH] + r * gh_s[b][j + 2*HH]);
                h1_s[b][j] = (1.0f - z) * n + z * h1_s[b][j];
            }
        }
        __syncthreads();

        // ---- Phase F: readout y = h1 @ w_out^T + b_out ; store sequence ----
        if (tid < BPB * II) {
            const int b = tid >> 5;   // /32
            const int i = tid & 31;
            float acc = __ldg(&bout[i]);
            const float4* wr = reinterpret_cast<const float4*>(wout + i * HH);
#pragma unroll 8
            for (int kk = 0; kk < HH / 4; ++kk) {
                const float4 w = __ldg(&wr[kk]);
                const float4 x = *reinterpret_cast<const float4*>(&h1_s[b][kk * 4]);
                acc = fmaf(w.x, x.x, acc);
                acc = fmaf(w.y, x.y, acc);
                acc = fmaf(w.z, x.z, acc);
                acc = fmaf(w.w, x.w, acc);
            }
            y_s[b][i] = acc;
            outseq[((long long)(b0 + b) * TM1 + t) * II + i] = acc;
        }
        __syncthreads();
    }

    // final hidden state of layer 1
    if (write_h1) {
        for (int i = tid; i < BPB * HH; i += NT) {
            const int b = i / HH;
            const int j = i % HH;
            outh1[(long long)(b0 + b) * HH + j] = h1_s[b][j];
        }
    }
}

extern "C" void kernel_launch(void* const* d_in, const int* in_sizes, int n_in,
                              void* d_out, int out_size) {
    const float* X    = (const float*)d_in[0];
    const float* ENC  = (const float*)d_in[1];
    const int*   MASK = (const int*)d_in[2];     // bool -> int32 per harness contract
    const float* wih0 = (const float*)d_in[3];
    const float* whh0 = (const float*)d_in[4];
    const float* bih0 = (const float*)d_in[5];
    const float* bhh0 = (const float*)d_in[6];
    const float* wih1 = (const float*)d_in[7];
    const float* whh1 = (const float*)d_in[8];
    const float* bih1 = (const float*)d_in[9];
    const float* bhh1 = (const float*)d_in[10];
    const float* wout = (const float*)d_in[11];
    const float* bout = (const float*)d_in[12];

    float* outseq = (float*)d_out;
    const int seqsz = BB * TM1 * II;            // output_sequence elements
    float* outh1  = outseq + seqsz;             // h1 appended after the sequence
    const int write_h1 = (out_size >= seqsz + BB * HH) ? 1 : 0;

    arrnn_kernel<<<NB, NT>>>(X, ENC, MASK,
                             wih0, whh0, bih0, bhh0,
                             wih1, whh1, bih1, bhh1,
                             wout, bout,
                             outseq, outh1, write_h1);
}

// round 3
// speedup vs baseline: 3.6981x; 3.6981x over previous
#include <cuda_runtime.h>
#include <cuda_fp16.h>

typedef unsigned long long ull;

// Problem constants
#define BB   512
#define TT   1024
#define TM1  1023
#define II   32
#define EE   32
#define HH   256
#define G3   768
#define KIN  64

#define BPB  4
#define NB   (BB / BPB)   // 128 blocks
#define NT   768

// ---- transposed fp16 weights, packed along k: WT[k/2][g] = (w[g][2k'], w[g][2k'+1]) ----
__device__ __half2 WI0T[KIN/2][G3];   //  96 KB
__device__ __half2 WH0T[HH/2][G3];    // 384 KB
__device__ __half2 WI1T[HH/2][G3];
__device__ __half2 WH1T[HH/2][G3];
__device__ float   WOUTT[HH][II];     // transposed readout, fp32 (tiny)

__global__ void prep_kernel(const float* __restrict__ wih0, const float* __restrict__ whh0,
                            const float* __restrict__ wih1, const float* __restrict__ whh1,
                            const float* __restrict__ wout)
{
    const int A  = (KIN/2) * G3;   // 24576
    const int Bn = (HH/2)  * G3;   // 98304
    int idx = blockIdx.x * blockDim.x + threadIdx.x;
    if (idx < A) {
        int k2 = idx / G3, g = idx % G3;
        WI0T[k2][g] = __floats2half2_rn(wih0[g*KIN + 2*k2], wih0[g*KIN + 2*k2 + 1]);
    } else if (idx < A + Bn) {
        int r = idx - A; int k2 = r / G3, g = r % G3;
        WH0T[k2][g] = __floats2half2_rn(whh0[g*HH + 2*k2], whh0[g*HH + 2*k2 + 1]);
    } else if (idx < A + 2*Bn) {
        int r = idx - A - Bn; int k2 = r / G3, g = r % G3;
        WI1T[k2][g] = __floats2half2_rn(wih1[g*HH + 2*k2], wih1[g*HH + 2*k2 + 1]);
    } else if (idx < A + 3*Bn) {
        int r = idx - A - 2*Bn; int k2 = r / G3, g = r % G3;
        WH1T[k2][g] = __floats2half2_rn(whh1[g*HH + 2*k2], whh1[g*HH + 2*k2 + 1]);
    } else if (idx < A + 3*Bn + HH*II) {
        int r = idx - A - 3*Bn; int k = r / II, i = r % II;
        WOUTT[k][i] = wout[i*HH + k];
    }
}

// ---- packed f32x2 helpers ----
__device__ __forceinline__ ull pack2(float a, float b) {
    ull r; asm("mov.b64 %0, {%1, %2};" : "=l"(r) : "f"(a), "f"(b)); return r;
}
__device__ __forceinline__ void unpack2(ull v, float& a, float& b) {
    asm("mov.b64 {%0, %1}, %2;" : "=f"(a), "=f"(b) : "l"(v));
}
__device__ __forceinline__ ull fma2(ull a, ull b, ull c) {
    ull d; asm("fma.rn.f32x2 %0, %1, %2, %3;" : "=l"(d) : "l"(a), "l"(b), "l"(c)); return d;
}
__device__ __forceinline__ float sigf(float x) {
    return __fdividef(1.0f, 1.0f + __expf(-x));
}
__device__ __forceinline__ float tanhfast(float x) {
    return 2.0f * sigf(2.0f * x) - 1.0f;
}

__global__ void __launch_bounds__(NT, 1)
arrnn_kernel(const float* __restrict__ X,
             const float* __restrict__ ENC,
             const int*   __restrict__ MASK,
             const float* __restrict__ bih0, const float* __restrict__ bhh0,
             const float* __restrict__ bih1, const float* __restrict__ bhh1,
             const float* __restrict__ bout,
             float* __restrict__ outseq, float* __restrict__ outh1,
             int write_h1)
{
    // activations packed 4 batches per row (16B rows -> one LDS.128 = both f32x2 pairs)
    __shared__ __align__(16) float inpp[KIN][4];
    __shared__ __align__(16) float h0p[HH][4];
    __shared__ __align__(16) float h1p[HH][4];
    __shared__ __align__(16) float gi2[G3][4];
    __shared__ __align__(16) float gh2[G3][4];
    __shared__ __align__(16) float yp[II][4];

    const int tid = threadIdx.x;
    const int b0  = blockIdx.x * BPB;
    const int g   = tid;

    for (int i = tid; i < HH * 4; i += NT) { (&h0p[0][0])[i] = 0.0f; (&h1p[0][0])[i] = 0.0f; }
    for (int i = tid; i < II * 4; i += NT) (&yp[0][0])[i] = 0.0f;
    __syncthreads();

    // packed biases (same bias in both halves of the batch pair)
    const ull bd_i0 = pack2(bih0[g], bih0[g]);
    const ull bd_h0 = pack2(bhh0[g], bhh0[g]);
    const ull bd_i1 = pack2(bih1[g], bih1[g]);
    const ull bd_h1 = pack2(bhh1[g], bhh1[g]);

    const __half2* pwi0 = &WI0T[0][g];
    const __half2* pwh0 = &WH0T[0][g];
    const __half2* pwi1 = &WI1T[0][g];
    const __half2* pwh1 = &WH1T[0][g];

    for (int t = 0; t < TM1; ++t) {
        // ---- Phase A: build packed input [x_or_y | enc(t+1)] ----
        if (tid < 2 * KIN) {
            const int p = tid >> 6;          // batch pair 0/1
            const int k = tid & 63;
            const int ba = 2*p, bb = 2*p + 1;
            const int gba = b0 + ba, gbb = b0 + bb;
            float v0, v1;
            if (k < II) {
                const bool k0 = (t == 0) || (MASK[gba * TT + t] != 0);
                const bool k1 = (t == 0) || (MASK[gbb * TT + t] != 0);
                v0 = k0 ? X[((size_t)gba * TT + t) * II + k] : yp[k][ba];
                v1 = k1 ? X[((size_t)gbb * TT + t) * II + k] : yp[k][bb];
            } else {
                v0 = ENC[((size_t)gba * TT + (t + 1)) * EE + (k - II)];
                v1 = ENC[((size_t)gbb * TT + (t + 1)) * EE + (k - II)];
            }
            inpp[k][ba] = v0;
            inpp[k][bb] = v1;
        }
        __syncthreads();

        // ---- Phase B: layer-0 gate pre-activations ----
        {
            ull agi0 = bd_i0, agi1 = bd_i0;
            ull agh0 = bd_h0, agh1 = bd_h0;
#pragma unroll 8
            for (int k2 = 0; k2 < KIN/2; ++k2) {
                const float2 wf = __half22float2(__ldg(pwi0 + k2 * G3));
                const ull wle = pack2(wf.x, wf.x);
                const ull wlo = pack2(wf.y, wf.y);
                const ulonglong2 xe = *reinterpret_cast<const ulonglong2*>(&inpp[2*k2][0]);
                const ulonglong2 xo = *reinterpret_cast<const ulonglong2*>(&inpp[2*k2+1][0]);
                agi0 = fma2(wle, xe.x, agi0);  agi1 = fma2(wle, xe.y, agi1);
                agi0 = fma2(wlo, xo.x, agi0);  agi1 = fma2(wlo, xo.y, agi1);
            }
#pragma unroll 8
            for (int k2 = 0; k2 < HH/2; ++k2) {
                const float2 wf = __half22float2(__ldg(pwh0 + k2 * G3));
                const ull wle = pack2(wf.x, wf.x);
                const ull wlo = pack2(wf.y, wf.y);
                const ulonglong2 xe = *reinterpret_cast<const ulonglong2*>(&h0p[2*k2][0]);
                const ulonglong2 xo = *reinterpret_cast<const ulonglong2*>(&h0p[2*k2+1][0]);
                agh0 = fma2(wle, xe.x, agh0);  agh1 = fma2(wle, xe.y, agh1);
                agh0 = fma2(wlo, xo.x, agh0);  agh1 = fma2(wlo, xo.y, agh1);
            }
            ulonglong2 si; si.x = agi0; si.y = agi1;
            ulonglong2 sh; sh.x = agh0; sh.y = agh1;
            *reinterpret_cast<ulonglong2*>(&gi2[g][0]) = si;
            *reinterpret_cast<ulonglong2*>(&gh2[g][0]) = sh;
        }
        __syncthreads();

        // ---- Phase C: layer-0 state update ----
        if (tid < 2 * HH) {
            const int j = tid >> 1;
            const int p = tid & 1;
            const float2 gir = *reinterpret_cast<const float2*>(&gi2[j      ][2*p]);
            const float2 ghr = *reinterpret_cast<const float2*>(&gh2[j      ][2*p]);
            const float2 giz = *reinterpret_cast<const float2*>(&gi2[j +  HH][2*p]);
            const float2 ghz = *reinterpret_cast<const float2*>(&gh2[j +  HH][2*p]);
            const float2 gin = *reinterpret_cast<const float2*>(&gi2[j + 2*HH][2*p]);
            const float2 ghn = *reinterpret_cast<const float2*>(&gh2[j + 2*HH][2*p]);
            float2 h = *reinterpret_cast<const float2*>(&h0p[j][2*p]);
            const float rx = sigf(gir.x + ghr.x), ry = sigf(gir.y + ghr.y);
            const float zx = sigf(giz.x + ghz.x), zy = sigf(giz.y + ghz.y);
            const float nx = tanhfast(gin.x + rx * ghn.x);
            const float ny = tanhfast(gin.y + ry * ghn.y);
            h.x = (1.0f - zx) * nx + zx * h.x;
            h.y = (1.0f - zy) * ny + zy * h.y;
            *reinterpret_cast<float2*>(&h0p[j][2*p]) = h;
        }
        __syncthreads();

        // ---- Phase D: layer-1 gate pre-activations ----
        {
            ull agi0 = bd_i1, agi1 = bd_i1;
            ull agh0 = bd_h1, agh1 = bd_h1;
#pragma unroll 8
            for (int k2 = 0; k2 < HH/2; ++k2) {
                const float2 wf = __half22float2(__ldg(pwi1 + k2 * G3));
                const ull wle = pack2(wf.x, wf.x);
                const ull wlo = pack2(wf.y, wf.y);
                const ulonglong2 xe = *reinterpret_cast<const ulonglong2*>(&h0p[2*k2][0]);
                const ulonglong2 xo = *reinterpret_cast<const ulonglong2*>(&h0p[2*k2+1][0]);
                agi0 = fma2(wle, xe.x, agi0);  agi1 = fma2(wle, xe.y, agi1);
                agi0 = fma2(wlo, xo.x, agi0);  agi1 = fma2(wlo, xo.y, agi1);
            }
#pragma unroll 8
            for (int k2 = 0; k2 < HH/2; ++k2) {
                const float2 wf = __half22float2(__ldg(pwh1 + k2 * G3));
                const ull wle = pack2(wf.x, wf.x);
                const ull wlo = pack2(wf.y, wf.y);
                const ulonglong2 xe = *reinterpret_cast<const ulonglong2*>(&h1p[2*k2][0]);
                const ulonglong2 xo = *reinterpret_cast<const ulonglong2*>(&h1p[2*k2+1][0]);
                agh0 = fma2(wle, xe.x, agh0);  agh1 = fma2(wle, xe.y, agh1);
                agh0 = fma2(wlo, xo.x, agh0);  agh1 = fma2(wlo, xo.y, agh1);
            }
            ulonglong2 si; si.x = agi0; si.y = agi1;
            ulonglong2 sh; sh.x = agh0; sh.y = agh1;
            *reinterpret_cast<ulonglong2*>(&gi2[g][0]) = si;
            *reinterpret_cast<ulonglong2*>(&gh2[g][0]) = sh;
        }
        __syncthreads();

        // ---- Phase E: layer-1 state update ----
        if (tid < 2 * HH) {
            const int j = tid >> 1;
            const int p = tid & 1;
            const float2 gir = *reinterpret_cast<const float2*>(&gi2[j      ][2*p]);
            const float2 ghr = *reinterpret_cast<const float2*>(&gh2[j      ][2*p]);
            const float2 giz = *reinterpret_cast<const float2*>(&gi2[j +  HH][2*p]);
            const float2 ghz = *reinterpret_cast<const float2*>(&gh2[j +  HH][2*p]);
            const float2 gin = *reinterpret_cast<const float2*>(&gi2[j + 2*HH][2*p]);
            const float2 ghn = *reinterpret_cast<const float2*>(&gh2[j + 2*HH][2*p]);
            float2 h = *reinterpret_cast<const float2*>(&h1p[j][2*p]);
            const float rx = sigf(gir.x + ghr.x), ry = sigf(gir.y + ghr.y);
            const float zx = sigf(giz.x + ghz.x), zy = sigf(giz.y + ghz.y);
            const float nx = tanhfast(gin.x + rx * ghn.x);
            const float ny = tanhfast(gin.y + ry * ghn.y);
            h.x = (1.0f - zx) * nx + zx * h.x;
            h.y = (1.0f - zy) * ny + zy * h.y;
            *reinterpret_cast<float2*>(&h1p[j][2*p]) = h;
        }
        __syncthreads();

        // ---- Phase F: readout + feedback + store ----
        if (tid < 2 * II) {
            const int p = tid >> 5;          // batch pair
            const int i = tid & 31;
            const float bo = __ldg(&bout[i]);
            ull a0 = pack2(bo, bo);
            ull a1 = pack2(0.0f, 0.0f);
            ull a2 = a1, a3 = a1;
#pragma unroll 8
            for (int k = 0; k < HH; k += 4) {
                const float w0 = WOUTT[k    ][i];
                const float w1 = WOUTT[k + 1][i];
                const float w2 = WOUTT[k + 2][i];
                const float w3 = WOUTT[k + 3][i];
                a0 = fma2(pack2(w0, w0), *reinterpret_cast<const ull*>(&h1p[k    ][2*p]), a0);
                a1 = fma2(pack2(w1, w1), *reinterpret_cast<const ull*>(&h1p[k + 1][2*p]), a1);
                a2 = fma2(pack2(w2, w2), *reinterpret_cast<const ull*>(&h1p[k + 2][2*p]), a2);
                a3 = fma2(pack2(w3, w3), *reinterpret_cast<const ull*>(&h1p[k + 3][2*p]), a3);
            }
            float s0x, s0y, s1x, s1y, s2x, s2y, s3x, s3y;
            unpack2(a0, s0x, s0y); unpack2(a1, s1x, s1y);
            unpack2(a2, s2x, s2y); unpack2(a3, s3x, s3y);
            const float y0 = (s0x + s1x) + (s2x + s3x);
            const float y1 = (s0y + s1y) + (s2y + s3y);
            yp[i][2*p]     = y0;
            yp[i][2*p + 1] = y1;
            outseq[((size_t)(b0 + 2*p    ) * TM1 + t) * II + i] = y0;
            outseq[((size_t)(b0 + 2*p + 1) * TM1 + t) * II + i] = y1;
        }
        __syncthreads();
    }

    if (write_h1) {
        for (int i = tid; i < BPB * HH; i += NT) {
            const int b = i >> 8;          // /HH
            const int j = i & (HH - 1);
            outh1[(size_t)(b0 + b) * HH + j] = h1p[j][b];
        }
    }
}

extern "C" void kernel_launch(void* const* d_in, const int* in_sizes, int n_in,
                              void* d_out, int out_size) {
    const float* X    = (const float*)d_in[0];
    const float* ENC  = (const float*)d_in[1];
    const int*   MASK = (const int*)d_in[2];
    const float* wih0 = (const float*)d_in[3];
    const float* whh0 = (const float*)d_in[4];
    const float* bih0 = (const float*)d_in[5];
    const float* bhh0 = (const float*)d_in[6];
    const float* wih1 = (const float*)d_in[7];
    const float* whh1 = (const float*)d_in[8];
    const float* bih1 = (const float*)d_in[9];
    const float* bhh1 = (const float*)d_in[10];
    const float* wout = (const float*)d_in[11];
    const float* bout = (const float*)d_in[12];

    float* outseq = (float*)d_out;
    const int seqsz = BB * TM1 * II;
    float* outh1  = outseq + seqsz;
    const int write_h1 = (out_size >= seqsz + BB * HH) ? 1 : 0;

    // one-time (per launch) weight transpose + fp16 cast
    const int total = (KIN/2)*G3 + 3*(HH/2)*G3 + HH*II;   // 327,680
    prep_kernel<<<(total + 255) / 256, 256>>>(wih0, whh0, wih1, whh1, wout);

    arrnn_kernel<<<NB, NT>>>(X, ENC, MASK,
                             bih0, bhh0, bih1, bhh1, bout,
                             outseq, outh1, write_h1);
}

// round 4
// speedup vs baseline: 4.6428x; 1.2554x over previous
#include <cuda_runtime.h>
#include <cuda_fp16.h>

typedef unsigned long long ull;

// Problem constants
#define BB   512
#define TT   1024
#define TM1  1023
#define II   32
#define EE   32
#define HH   256
#define G3   768
#define KIN  64

#define BPB  4
#define NB   (BB / BPB)   // 128 blocks
#define NT   384          // 2 gate rows per thread

// ---- transposed fp16 weights, 16B-grouped along k: W[k/8][g][j] = half2(k=8kb+2j, 8kb+2j+1) ----
__device__ __align__(16) __half2 W4I0[KIN/8][G3][4];
__device__ __align__(16) __half2 W4H0[HH /8][G3][4];
__device__ __align__(16) __half2 W4I1[HH /8][G3][4];
__device__ __align__(16) __half2 W4H1[HH /8][G3][4];
__device__ float WOUTT[HH][II];

__global__ void prep_kernel(const float* __restrict__ wih0, const float* __restrict__ whh0,
                            const float* __restrict__ wih1, const float* __restrict__ whh1,
                            const float* __restrict__ wout)
{
    const int S0 = (KIN/8) * G3;   // 6144
    const int S1 = (HH /8) * G3;   // 24576
    int idx = blockIdx.x * blockDim.x + threadIdx.x;
    if (idx < S0) {
        int k8 = idx / G3, g = idx % G3;
        const float* b = wih0 + g * KIN + 8 * k8;
#pragma unroll
        for (int j = 0; j < 4; ++j) W4I0[k8][g][j] = __floats2half2_rn(b[2*j], b[2*j+1]);
    } else if (idx < S0 + S1) {
        int r = idx - S0; int k8 = r / G3, g = r % G3;
        const float* b = whh0 + g * HH + 8 * k8;
#pragma unroll
        for (int j = 0; j < 4; ++j) W4H0[k8][g][j] = __floats2half2_rn(b[2*j], b[2*j+1]);
    } else if (idx < S0 + 2*S1) {
        int r = idx - S0 - S1; int k8 = r / G3, g = r % G3;
        const float* b = wih1 + g * HH + 8 * k8;
#pragma unroll
        for (int j = 0; j < 4; ++j) W4I1[k8][g][j] = __floats2half2_rn(b[2*j], b[2*j+1]);
    } else if (idx < S0 + 3*S1) {
        int r = idx - S0 - 2*S1; int k8 = r / G3, g = r % G3;
        const float* b = whh1 + g * HH + 8 * k8;
#pragma unroll
        for (int j = 0; j < 4; ++j) W4H1[k8][g][j] = __floats2half2_rn(b[2*j], b[2*j+1]);
    } else if (idx < S0 + 3*S1 + HH*II) {
        int r = idx - S0 - 3*S1; int k = r / II, i = r % II;
        WOUTT[k][i] = wout[i*HH + k];
    }
}

// ---- packed f32x2 helpers ----
__device__ __forceinline__ ull pack2(float a, float b) {
    ull r; asm("mov.b64 %0, {%1, %2};" : "=l"(r) : "f"(a), "f"(b)); return r;
}
__device__ __forceinline__ void unpack2(ull v, float& a, float& b) {
    asm("mov.b64 {%0, %1}, %2;" : "=f"(a), "=f"(b) : "l"(v));
}
__device__ __forceinline__ ull fma2(ull a, ull b, ull c) {
    ull d; asm("fma.rn.f32x2 %0, %1, %2, %3;" : "=l"(d) : "l"(a), "l"(b), "l"(c)); return d;
}
__device__ __forceinline__ float sigf(float x) {
    return __fdividef(1.0f, 1.0f + __expf(-x));
}
__device__ __forceinline__ float tanhfast(float x) {
    return 2.0f * sigf(2.0f * x) - 1.0f;
}

// dual-row packed GEMV accumulate: acc[row][batchpair] over NK8*8 k-values
template<int NK8>
__device__ __forceinline__ void gemv2(const __half2 (*__restrict__ W)[G3][4],
                                      const float (*act)[4],
                                      int ga, int gb, ull acc[2][2])
{
#pragma unroll 4
    for (int kb = 0; kb < NK8; ++kb) {
        const uint4 wa = *reinterpret_cast<const uint4*>(&W[kb][ga][0]);
        const uint4 wb = *reinterpret_cast<const uint4*>(&W[kb][gb][0]);
#pragma unroll
        for (int j = 0; j < 4; ++j) {
            const float2 fa = __half22float2(reinterpret_cast<const __half2*>(&wa)[j]);
            const float2 fb = __half22float2(reinterpret_cast<const __half2*>(&wb)[j]);
            const int k = kb * 8 + 2 * j;
            const ulonglong2 xe = *reinterpret_cast<const ulonglong2*>(&act[k    ][0]);
            const ulonglong2 xo = *reinterpret_cast<const ulonglong2*>(&act[k + 1][0]);
            const ull wae = pack2(fa.x, fa.x), wao = pack2(fa.y, fa.y);
            const ull wbe = pack2(fb.x, fb.x), wbo = pack2(fb.y, fb.y);
            acc[0][0] = fma2(wae, xe.x, acc[0][0]);
            acc[0][1] = fma2(wae, xe.y, acc[0][1]);
            acc[1][0] = fma2(wbe, xe.x, acc[1][0]);
            acc[1][1] = fma2(wbe, xe.y, acc[1][1]);
            acc[0][0] = fma2(wao, xo.x, acc[0][0]);
            acc[0][1] = fma2(wao, xo.y, acc[0][1]);
            acc[1][0] = fma2(wbo, xo.x, acc[1][0]);
            acc[1][1] = fma2(wbo, xo.y, acc[1][1]);
        }
    }
}

__device__ __forceinline__ void gate4(const float4 gir, const float4 ghr,
                                      const float4 giz, const float4 ghz,
                                      const float4 gin, const float4 ghn,
                                      float4& h)
{
    const float r0 = sigf(gir.x + ghr.x), r1 = sigf(gir.y + ghr.y);
    const float r2 = sigf(gir.z + ghr.z), r3 = sigf(gir.w + ghr.w);
    const float z0 = sigf(giz.x + ghz.x), z1 = sigf(giz.y + ghz.y);
    const float z2 = sigf(giz.z + ghz.z), z3 = sigf(giz.w + ghz.w);
    const float n0 = tanhfast(gin.x + r0 * ghn.x);
    const float n1 = tanhfast(gin.y + r1 * ghn.y);
    const float n2 = tanhfast(gin.z + r2 * ghn.z);
    const float n3 = tanhfast(gin.w + r3 * ghn.w);
    h.x = (1.0f - z0) * n0 + z0 * h.x;
    h.y = (1.0f - z1) * n1 + z1 * h.y;
    h.z = (1.0f - z2) * n2 + z2 * h.z;
    h.w = (1.0f - z3) * n3 + z3 * h.w;
}

__global__ void __launch_bounds__(NT, 1)
arrnn_kernel(const float* __restrict__ X,
             const float* __restrict__ ENC,
             const int*   __restrict__ MASK,
             const float* __restrict__ bih0, const float* __restrict__ bhh0,
             const float* __restrict__ bih1, const float* __restrict__ bhh1,
             const float* __restrict__ bout,
             float* __restrict__ outseq, float* __restrict__ outh1,
             int write_h1)
{
    __shared__ __align__(16) float inpp[KIN][4];
    __shared__ __align__(16) float h0p[HH][4];
    __shared__ __align__(16) float h1p[HH][4];
    __shared__ __align__(16) float gi2[G3][4];
    __shared__ __align__(16) float gh2[G3][4];
    __shared__ __align__(16) float yp[II][4];

    const int tid = threadIdx.x;
    const int b0  = blockIdx.x * BPB;
    const int ga  = tid;          // gate row A
    const int gb  = tid + NT;     // gate row B

    for (int i = tid; i < HH * 4; i += NT) { (&h0p[0][0])[i] = 0.0f; (&h1p[0][0])[i] = 0.0f; }
    for (int i = tid; i < II * 4; i += NT) (&yp[0][0])[i] = 0.0f;
    __syncthreads();

    const ull bi0a = pack2(bih0[ga], bih0[ga]), bi0b = pack2(bih0[gb], bih0[gb]);
    const ull bh0a = pack2(bhh0[ga], bhh0[ga]), bh0b = pack2(bhh0[gb], bhh0[gb]);
    const ull bi1a = pack2(bih1[ga], bih1[ga]), bi1b = pack2(bih1[gb], bih1[gb]);
    const ull bh1a = pack2(bhh1[ga], bhh1[ga]), bh1b = pack2(bhh1[gb], bhh1[gb]);

    for (int t = 0; t < TM1; ++t) {
        // ---- Phase A: build packed input [x_or_y | enc(t+1)] ----
        if (tid < 2 * KIN) {
            const int p = tid >> 6;
            const int k = tid & 63;
            const int ba = 2*p, bb = 2*p + 1;
            const int gba = b0 + ba, gbb = b0 + bb;
            float v0, v1;
            if (k < II) {
                const bool k0 = (t == 0) || (MASK[gba * TT + t] != 0);
                const bool k1 = (t == 0) || (MASK[gbb * TT + t] != 0);
                v0 = k0 ? X[((size_t)gba * TT + t) * II + k] : yp[k][ba];
                v1 = k1 ? X[((size_t)gbb * TT + t) * II + k] : yp[k][bb];
            } else {
                v0 = ENC[((size_t)gba * TT + (t + 1)) * EE + (k - II)];
                v1 = ENC[((size_t)gbb * TT + (t + 1)) * EE + (k - II)];
            }
            inpp[k][ba] = v0;
            inpp[k][bb] = v1;
        }
        __syncthreads();

        // ---- Phase B: layer-0 gate pre-activations (2 rows per thread) ----
        {
            ull ai[2][2] = {{bi0a, bi0a}, {bi0b, bi0b}};
            gemv2<KIN/8>(W4I0, inpp, ga, gb, ai);
            ull ah[2][2] = {{bh0a, bh0a}, {bh0b, bh0b}};
            gemv2<HH/8>(W4H0, h0p, ga, gb, ah);
            ulonglong2 v;
            v.x = ai[0][0]; v.y = ai[0][1];
            *reinterpret_cast<ulonglong2*>(&gi2[ga][0]) = v;
            v.x = ai[1][0]; v.y = ai[1][1];
            *reinterpret_cast<ulonglong2*>(&gi2[gb][0]) = v;
            v.x = ah[0][0]; v.y = ah[0][1];
            *reinterpret_cast<ulonglong2*>(&gh2[ga][0]) = v;
            v.x = ah[1][0]; v.y = ah[1][1];
            *reinterpret_cast<ulonglong2*>(&gh2[gb][0]) = v;
        }
        __syncthreads();

        // ---- Phase C: layer-0 state update (float4 over batch) ----
        if (tid < HH) {
            const int j = tid;
            float4 h = *reinterpret_cast<const float4*>(&h0p[j][0]);
            gate4(*reinterpret_cast<const float4*>(&gi2[j        ][0]),
                  *reinterpret_cast<const float4*>(&gh2[j        ][0]),
                  *reinterpret_cast<const float4*>(&gi2[j +   HH ][0]),
                  *reinterpret_cast<const float4*>(&gh2[j +   HH ][0]),
                  *reinterpret_cast<const float4*>(&gi2[j + 2*HH ][0]),
                  *reinterpret_cast<const float4*>(&gh2[j + 2*HH ][0]), h);
            *reinterpret_cast<float4*>(&h0p[j][0]) = h;
        }
        __syncthreads();

        // ---- Phase D: layer-1 gate pre-activations ----
        {
            ull ai[2][2] = {{bi1a, bi1a}, {bi1b, bi1b}};
            gemv2<HH/8>(W4I1, h0p, ga, gb, ai);
            ull ah[2][2] = {{bh1a, bh1a}, {bh1b, bh1b}};
            gemv2<HH/8>(W4H1, h1p, ga, gb, ah);
            ulonglong2 v;
            v.x = ai[0][0]; v.y = ai[0][1];
            *reinterpret_cast<ulonglong2*>(&gi2[ga][0]) = v;
            v.x = ai[1][0]; v.y = ai[1][1];
            *reinterpret_cast<ulonglong2*>(&gi2[gb][0]) = v;
            v.x = ah[0][0]; v.y = ah[0][1];
            *reinterpret_cast<ulonglong2*>(&gh2[ga][0]) = v;
            v.x = ah[1][0]; v.y = ah[1][1];
            *reinterpret_cast<ulonglong2*>(&gh2[gb][0]) = v;
        }
        __syncthreads();

        // ---- Phase E: layer-1 state update ----
        if (tid < HH) {
            const int j = tid;
            float4 h = *reinterpret_cast<const float4*>(&h1p[j][0]);
            gate4(*reinterpret_cast<const float4*>(&gi2[j        ][0]),
                  *reinterpret_cast<const float4*>(&gh2[j        ][0]),
                  *reinterpret_cast<const float4*>(&gi2[j +   HH ][0]),
                  *reinterpret_cast<const float4*>(&gh2[j +   HH ][0]),
                  *reinterpret_cast<const float4*>(&gi2[j + 2*HH ][0]),
                  *reinterpret_cast<const float4*>(&gh2[j + 2*HH ][0]), h);
            *reinterpret_cast<float4*>(&h1p[j][0]) = h;
        }
        __syncthreads();

        // ---- Phase F: readout + feedback + store ----
        if (tid < 2 * II) {
            const int p = tid >> 5;
            const int i = tid & 31;
            const float bo = __ldg(&bout[i]);
            ull a0 = pack2(bo, bo);
            ull a1 = pack2(0.0f, 0.0f);
            ull a2 = a1, a3 = a1;
#pragma unroll 8
            for (int k = 0; k < HH; k += 4) {
                const float w0 = WOUTT[k    ][i];
                const float w1 = WOUTT[k + 1][i];
                const float w2 = WOUTT[k + 2][i];
                const float w3 = WOUTT[k + 3][i];
                a0 = fma2(pack2(w0, w0), *reinterpret_cast<const ull*>(&h1p[k    ][2*p]), a0);
                a1 = fma2(pack2(w1, w1), *reinterpret_cast<const ull*>(&h1p[k + 1][2*p]), a1);
                a2 = fma2(pack2(w2, w2), *reinterpret_cast<const ull*>(&h1p[k + 2][2*p]), a2);
                a3 = fma2(pack2(w3, w3), *reinterpret_cast<const ull*>(&h1p[k + 3][2*p]), a3);
            }
            float s0x, s0y, s1x, s1y, s2x, s2y, s3x, s3y;
            unpack2(a0, s0x, s0y); unpack2(a1, s1x, s1y);
            unpack2(a2, s2x, s2y); unpack2(a3, s3x, s3y);
            const float y0 = (s0x + s1x) + (s2x + s3x);
            const float y1 = (s0y + s1y) + (s2y + s3y);
            yp[i][2*p]     = y0;
            yp[i][2*p + 1] = y1;
            outseq[((size_t)(b0 + 2*p    ) * TM1 + t) * II + i] = y0;
            outseq[((size_t)(b0 + 2*p + 1) * TM1 + t) * II + i] = y1;
        }
        __syncthreads();
    }

    if (write_h1) {
        for (int i = tid; i < BPB * HH; i += NT) {
            const int b = i >> 8;
            const int j = i & (HH - 1);
            outh1[(size_t)(b0 + b) * HH + j] = h1p[j][b];
        }
    }
}

extern "C" void kernel_launch(void* const* d_in, const int* in_sizes, int n_in,
                              void* d_out, int out_size) {
    const float* X    = (const float*)d_in[0];
    const float* ENC  = (const float*)d_in[1];
    const int*   MASK = (const int*)d_in[2];
    const float* wih0 = (const float*)d_in[3];
    const float* whh0 = (const float*)d_in[4];
    const float* bih0 = (const float*)d_in[5];
    const float* bhh0 = (const float*)d_in[6];
    const float* wih1 = (const float*)d_in[7];
    const float* whh1 = (const float*)d_in[8];
    const float* bih1 = (const float*)d_in[9];
    const float* bhh1 = (const float*)d_in[10];
    const float* wout = (const float*)d_in[11];
    const float* bout = (const float*)d_in[12];

    float* outseq = (float*)d_out;
    const int seqsz = BB * TM1 * II;
    float* outh1  = outseq + seqsz;
    const int write_h1 = (out_size >= seqsz + BB * HH) ? 1 : 0;

    const int total = (KIN/8)*G3 + 3*(HH/8)*G3 + HH*II;   // 88064
    prep_kernel<<<(total + 255) / 256, 256>>>(wih0, whh0, wih1, whh1, wout);

    arrnn_kernel<<<NB, NT>>>(X, ENC, MASK,
                             bih0, bhh0, bih1, bhh1, bout,
                             outseq, outh1, write_h1);
}